// round 16
// baseline (speedup 1.0000x reference)
#include <cuda_runtime.h>
#include <cuda_fp16.h>
#include <cstdint>

// Problem constants (fixed by the dataset)
#define BB     2
#define CIN    32
#define COUT   32
#define KS     9
#define NIN    16384
#define NOUT   16384
#define NNZMAX 1500000
#define CAPK   40               // per-(out,k) bin capacity; Poisson(10.2) -> ~7 sigma
#define KPAD   16               // cursor/bin k-stride padding
#define NJ     288              // KS*32 mix inner dimension

#define ZSCALE     16384.0f     // 2^14: lift xq (~6e-5) into fp16 normal range
#define ZSCALE_INV 6.103515625e-05f   // 2^-14, exact

#define GBLK   1184             // gather blocks (8/SM)
#define GWARPS (GBLK * 8)
#define NSEGP  ((KS * NOUT) / 2) // segment PAIRS = 73728

typedef unsigned long long ull;

__device__ __forceinline__ ull pack2(float lo, float hi) {
    ull r; asm("mov.b64 %0,{%1,%2};" : "=l"(r) : "f"(lo), "f"(hi)); return r;
}
__device__ __forceinline__ void unpack2(ull v, float& lo, float& hi) {
    asm("mov.b64 {%0,%1},%2;" : "=f"(lo), "=f"(hi) : "l"(v));
}
__device__ __forceinline__ void fma2(ull& d, ull a, ull b) {
    asm("fma.rn.f32x2 %0,%1,%2,%0;" : "+l"(d) : "l"(a), "l"(b));
}

// ---------------- scratch (device globals; no allocation allowed) ----------
__device__ __half  g_xqh[NIN * 64];                  // [i][c]{b0,b1} fp16          (2 MB)
__device__ ull     g_wpair[NJ * 32];                 // [j][o] = {w,w}*2^-14        (72 KB)
__device__ int     g_cur[NOUT * KPAD];               // per-(out,k) cursors         (1 MB)
__device__ int2    g_bin[(size_t)NOUT * KPAD * CAPK];// {in, psi bits}              (84 MB)
__device__ float2  g_Y[(size_t)NOUT * NJ];           // [n][j] = {y_b0, y_b1}       (37.7 MB)

// ---------------- K1: transpose x*(qw*2^14) -> xqh[i][c]{b} fp16 ------------
__global__ void k_xqT(const float* __restrict__ x, const float* __restrict__ qw) {
    __shared__ float tile[32][33];
    int i0 = blockIdx.x * 32;
    int r0 = blockIdx.y * 32;                 // r = b*32+c, 0..63
    int r = r0 + threadIdx.y;
    int i = i0 + threadIdx.x;
    tile[threadIdx.y][threadIdx.x] = x[(size_t)r * NIN + i];
    __syncthreads();
    int iw = i0 + threadIdx.y;
    int rr = r0 + threadIdx.x;
    int c = rr & 31, b = rr >> 5;
    float v = tile[threadIdx.x][threadIdx.y] * (qw[iw] * ZSCALE);
    g_xqh[((size_t)iw * 32 + c) * 2 + b] = __float2half_rn(v);
}

// ---------------- K2: weight -> packed pairs {w,w} * 2^-14 ------------------
__global__ void k_wpair(const float* __restrict__ weight) {
    int idx = blockIdx.x * blockDim.x + threadIdx.x;
    if (idx < NJ * 32) {
        int o = idx & 31;
        int j = idx >> 5;
        int k = j >> 5;
        int c = j & 31;
        float w = weight[o * (CIN * KS) + c * KS + k] * ZSCALE_INV;
        g_wpair[idx] = pack2(w, w);
    }
}

// ---------------- K3: scatter into (out,k) bins, 4 entries/thread ----------
__global__ void k_scatter4(const int4* __restrict__ idx_k,
                           const int4* __restrict__ idx_out,
                           const int4* __restrict__ idx_in,
                           const float4* __restrict__ psi, int nq) {
    int t = blockIdx.x * blockDim.x + threadIdx.x;
    if (t < nq) {
        int4   kk = idx_k[t];
        int4   oo = idx_out[t];
        int4   ii = idx_in[t];
        float4 pp = psi[t];
        int b0 = (oo.x << 4) + kk.x;
        int b1 = (oo.y << 4) + kk.y;
        int b2 = (oo.z << 4) + kk.z;
        int b3 = (oo.w << 4) + kk.w;
        int p0 = atomicAdd(&g_cur[b0], 1);
        int p1 = atomicAdd(&g_cur[b1], 1);
        int p2 = atomicAdd(&g_cur[b2], 1);
        int p3 = atomicAdd(&g_cur[b3], 1);
        if (p0 < CAPK) g_bin[(size_t)b0 * CAPK + p0] = make_int2(ii.x, __float_as_int(pp.x));
        if (p1 < CAPK) g_bin[(size_t)b1 * CAPK + p1] = make_int2(ii.y, __float_as_int(pp.y));
        if (p2 < CAPK) g_bin[(size_t)b2 * CAPK + p2] = make_int2(ii.z, __float_as_int(pp.z));
        if (p3 < CAPK) g_bin[(size_t)b3 * CAPK + p3] = make_int2(ii.w, __float_as_int(pp.w));
    }
}

__global__ void k_scatter_tail(const int* __restrict__ idx_k,
                               const int* __restrict__ idx_out,
                               const int* __restrict__ idx_in,
                               const float* __restrict__ psi,
                               int start, int nnz) {
    int e = start + blockIdx.x * blockDim.x + threadIdx.x;
    if (e < nnz) {
        int b = (idx_out[e] << 4) + idx_k[e];
        int p = atomicAdd(&g_cur[b], 1);
        if (p < CAPK)
            g_bin[(size_t)b * CAPK + p] = make_int2(idx_in[e], __float_as_int(psi[e]));
    }
}

// ---------------- K4: full-N streaming gather, 2 segments per warp ----------
// Two independent load chains in flight per warp; no smem, no barriers.
__global__ void __launch_bounds__(256, 8) k_gather_seg() {
    int W    = blockIdx.x * 8 + (threadIdx.x >> 5);
    int lane = threadIdx.x & 31;
    const __half2* __restrict__ xq2 = (const __half2*)g_xqh;

    for (int u = W; u < NSEGP; u += GWARPS) {
        int sA = u * 2, sB = sA + 1;
        int nA = sA & (NOUT - 1), kA = sA >> 14;
        int nB = sB & (NOUT - 1), kB = sB >> 14;
        int binA = (nA << 4) + kA;
        int binB = (nB << 4) + kB;

        int cA = g_cur[binA]; if (cA > CAPK) cA = CAPK;
        int cB = g_cur[binB]; if (cB > CAPK) cB = CAPK;
        const int4* segA = (const int4*)&g_bin[(size_t)binA * CAPK];
        const int4* segB = (const int4*)&g_bin[(size_t)binB * CAPK];

        float a0 = 0.f, a1 = 0.f, b0 = 0.f, b1 = 0.f;
        int pA = cA >> 1, pB = cB >> 1;
        int pmax = pA > pB ? pA : pB;

        for (int m = 0; m < pmax; m++) {
            if (m < pA) {                      // chain A: 2 entries
                int4 q = segA[m];
                float2 f0 = __half22float2(xq2[(q.x << 5) + lane]);
                float2 f1 = __half22float2(xq2[(q.z << 5) + lane]);
                float w0 = __int_as_float(q.y), w1 = __int_as_float(q.w);
                a0 = fmaf(w0, f0.x, a0); a1 = fmaf(w0, f0.y, a1);
                a0 = fmaf(w1, f1.x, a0); a1 = fmaf(w1, f1.y, a1);
            }
            if (m < pB) {                      // chain B: independent
                int4 q = segB[m];
                float2 f0 = __half22float2(xq2[(q.x << 5) + lane]);
                float2 f1 = __half22float2(xq2[(q.z << 5) + lane]);
                float w0 = __int_as_float(q.y), w1 = __int_as_float(q.w);
                b0 = fmaf(w0, f0.x, b0); b1 = fmaf(w0, f0.y, b1);
                b0 = fmaf(w1, f1.x, b0); b1 = fmaf(w1, f1.y, b1);
            }
        }
        if (cA & 1) {
            int2 e = ((const int2*)segA)[cA - 1];
            float2 f = __half22float2(xq2[(e.x << 5) + lane]);
            float ps = __int_as_float(e.y);
            a0 = fmaf(ps, f.x, a0); a1 = fmaf(ps, f.y, a1);
        }
        if (cB & 1) {
            int2 e = ((const int2*)segB)[cB - 1];
            float2 f = __half22float2(xq2[(e.x << 5) + lane]);
            float ps = __int_as_float(e.y);
            b0 = fmaf(ps, f.x, b0); b1 = fmaf(ps, f.y, b1);
        }

        g_Y[(size_t)nA * NJ + kA * 32 + lane] = make_float2(a0, a1);
        g_Y[(size_t)nB * NJ + kB * 32 + lane] = make_float2(b0, b1);
    }
}

// ---------------- K5: mix GEMM, full N (256 blocks, one resident wave) ------
// block 256 thr; tile 64 n x 32 o; 9 j-chunks of 32. f32x2 packed math.
#define SYS 34                   // ull stride (16B-aligned rows)
__global__ void __launch_bounds__(256) k_mix(const float* __restrict__ bias,
                                             float* __restrict__ out) {
    __shared__ ull smem_u[(64 + 32) * SYS];   // sy[64][34] | sw[32][34] (25.5KB)
    ull* sy = smem_u;
    ull* sw = smem_u + 64 * SYS;
    float* tile = (float*)smem_u;             // epilogue reuse: [64 bo][65]

    int tid = threadIdx.x;
    int tr  = tid >> 4;                       // 0..15
    int tc  = tid & 15;                       // 0..15
    int n0  = blockIdx.x * 64;

    float bias0 = bias[2 * tc];
    float bias1 = bias[2 * tc + 1];

    ull acc[4][2];
#pragma unroll
    for (int r = 0; r < 4; r++) { acc[r][0] = 0ull; acc[r][1] = 0ull; }

    const ull* __restrict__ Yg = (const ull*)g_Y;

    for (int kc = 0; kc < 9; kc++) {
        int j0 = kc * 32;
        // stage Y chunk: 64n x 32j ull
#pragma unroll
        for (int t = 0; t < 8; t += 2) {       // 4 float4 per thread
            int u = tid * 8 + t;               // even -> 16B aligned
            int nl = u >> 5, jj = u & 31;
            *(float4*)&sy[nl * SYS + jj] =
                *(const float4*)&Yg[(size_t)(n0 + nl) * NJ + j0 + jj];
        }
        // stage W chunk: 32j x 32o ull
#pragma unroll
        for (int t = 0; t < 4; t += 2) {
            int u = tid * 4 + t;
            int j = u >> 5, o = u & 31;
            *(float4*)&sw[j * SYS + o] = *(const float4*)&g_wpair[(j0 + j) * 32 + o];
        }
        __syncthreads();

#pragma unroll 8
        for (int jj = 0; jj < 32; jj++) {
            ull w0 = sw[jj * SYS + 2 * tc];
            ull w1 = sw[jj * SYS + 2 * tc + 1];
#pragma unroll
            for (int r = 0; r < 4; r++) {
                ull yv = sy[(tr + 16 * r) * SYS + jj];   // broadcast LDS.64
                fma2(acc[r][0], yv, w0);
                fma2(acc[r][1], yv, w1);
            }
        }
        __syncthreads();
    }

    // epilogue: unpack, +bias, transpose via smem, coalesced store
#pragma unroll
    for (int r = 0; r < 4; r++) {
        int nl = tr + 16 * r;
        float v00, v01, v10, v11;
        unpack2(acc[r][0], v00, v01);         // o=2tc: {b0,b1}
        unpack2(acc[r][1], v10, v11);         // o=2tc+1
        tile[(0 * 32 + 2 * tc) * 65 + nl]     = v00 + bias0;
        tile[(1 * 32 + 2 * tc) * 65 + nl]     = v01 + bias0;
        tile[(0 * 32 + 2 * tc + 1) * 65 + nl] = v10 + bias1;
        tile[(1 * 32 + 2 * tc + 1) * 65 + nl] = v11 + bias1;
    }
    __syncthreads();
    for (int u = tid; u < 64 * 64; u += 256) {
        int bo = u >> 6;
        int nn = u & 63;
        out[(size_t)bo * NOUT + n0 + nn] = tile[bo * 65 + nn];
    }
}

// ---------------- launch: prep || scatter fork, then serial gather -> mix ---
extern "C" void kernel_launch(void* const* d_in, const int* in_sizes, int n_in,
                              void* d_out, int out_size) {
    const float* x    = (const float*)d_in[0];
    const float* qw   = (const float*)d_in[1];
    const float* psi  = (const float*)d_in[2];
    const float* wgt  = (const float*)d_in[3];
    const float* bias = (const float*)d_in[4];
    const int* idx_k  = (const int*)d_in[5];
    const int* idx_o  = (const int*)d_in[6];
    const int* idx_i  = (const int*)d_in[7];
    int nnz = in_sizes[2];
    float* out = (float*)d_out;

    cudaStream_t s0 = 0;
    cudaStream_t s1;
    cudaStreamCreateWithFlags(&s1, cudaStreamNonBlocking);
    cudaEvent_t evA, evS;
    cudaEventCreateWithFlags(&evA, cudaEventDisableTiming);
    cudaEventCreateWithFlags(&evS, cudaEventDisableTiming);

    int* cur_ptr;
    cudaGetSymbolAddress((void**)&cur_ptr, g_cur);

    // fork s1 from s0
    cudaEventRecord(evA, s0);
    cudaStreamWaitEvent(s1, evA, 0);

    // s1: cursor reset + scatter (depends only on idx arrays)
    cudaMemsetAsync(cur_ptr, 0, NOUT * KPAD * sizeof(int), s1);
    int nq = nnz >> 2;
    k_scatter4<<<(nq + 255) / 256, 256, 0, s1>>>(
        (const int4*)idx_k, (const int4*)idx_o, (const int4*)idx_i,
        (const float4*)psi, nq);
    int rem = nnz - (nq << 2);
    if (rem > 0)
        k_scatter_tail<<<1, 256, 0, s1>>>(idx_k, idx_o, idx_i, psi, nq << 2, nnz);
    cudaEventRecord(evS, s1);

    // s0: xq + wpair prep (overlaps scatter)
    dim3 tb(32, 32);
    k_xqT<<<dim3(NIN / 32, 64 / 32), tb, 0, s0>>>(x, qw);
    k_wpair<<<(NJ * 32 + 255) / 256, 256, 0, s0>>>(wgt);

    // join, then serial gather -> mix (each one full-GPU balanced wave)
    cudaStreamWaitEvent(s0, evS, 0);
    k_gather_seg<<<GBLK, 256, 0, s0>>>();
    k_mix<<<NOUT / 64, 256, 0, s0>>>(bias, out);
}

// round 17
// speedup vs baseline: 1.2137x; 1.2137x over previous
#include <cuda_runtime.h>
#include <cuda_fp16.h>
#include <cstdint>

// Problem constants (fixed by the dataset)
#define BB     2
#define CIN    32
#define COUT   32
#define KS     9
#define NIN    16384
#define NOUT   16384
#define NNZMAX 1500000
#define CAPK   40               // per-(out,k) bin capacity; Poisson(10.2) -> ~7 sigma
#define KPAD   16               // cursor/bin k-stride padding

#define ZSCALE     16384.0f     // 2^14: lift y (~2e-4 region) into fp16 normal range
#define ZSCALE_INV 6.103515625e-05f   // 2^-14, exact

// ---------------- scratch (device globals; no allocation allowed) ----------
__device__ float2 g_xqf[NIN * 32];                   // [i][c] = {b0,b1} fp32*2^14  (4 MB)
__device__ float  g_wT2[KS * 32 * 32];               // pair-interleaved, *2^-14    (36 KB)
__device__ int    g_cur[NOUT * KPAD];                // per-(out,k) cursors         (1 MB)
__device__ int2   g_bin[(size_t)NOUT * KPAD * CAPK]; // {in, psi bits}              (84 MB)

// ---------------- K1: transpose x*(qw*2^14) -> xqf[i][c]{b0,b1} fp32 --------
__global__ void k_xqT(const float* __restrict__ x, const float* __restrict__ qw) {
    __shared__ float tile[32][33];
    int i0 = blockIdx.x * 32;
    int r0 = blockIdx.y * 32;                 // r = b*32+c, 0..63
    int r = r0 + threadIdx.y;
    int i = i0 + threadIdx.x;
    tile[threadIdx.y][threadIdx.x] = x[(size_t)r * NIN + i];
    __syncthreads();
    int iw = i0 + threadIdx.y;
    int rr = r0 + threadIdx.x;
    int c = rr & 31, b = rr >> 5;
    float v = tile[threadIdx.x][threadIdx.y] * (qw[iw] * ZSCALE);
    ((float*)g_xqf)[((size_t)iw * 32 + c) * 2 + b] = v;
}

// ---------------- K2: weight -> pair-interleaved wT2, ZSCALE_INV folded -----
// j = k*32+c; pair jj = j>>1, t = j&1. wT2[jj*64 + o*2 + t] = W[o][c][k] * 2^-14
__global__ void k_wT2(const float* __restrict__ weight) {
    int idx = blockIdx.x * blockDim.x + threadIdx.x;
    if (idx < KS * 32 * 32) {
        int t  = idx & 1;
        int o  = (idx >> 1) & 31;
        int jj = idx >> 6;
        int j  = 2 * jj + t;
        int k  = j >> 5;
        int c  = j & 31;
        g_wT2[idx] = weight[o * (CIN * KS) + c * KS + k] * ZSCALE_INV;
    }
}

// ---------------- K3: scatter, 8 entries/thread (8 ATOMGs in flight) --------
__global__ void k_scatter8(const int4* __restrict__ idx_k,
                           const int4* __restrict__ idx_out,
                           const int4* __restrict__ idx_in,
                           const float4* __restrict__ psi, int nq8) {
    int t = blockIdx.x * blockDim.x + threadIdx.x;
    if (t < nq8) {
        int4   kkA = idx_k[2 * t],     kkB = idx_k[2 * t + 1];
        int4   ooA = idx_out[2 * t],   ooB = idx_out[2 * t + 1];
        int4   iiA = idx_in[2 * t],    iiB = idx_in[2 * t + 1];
        float4 ppA = psi[2 * t],       ppB = psi[2 * t + 1];
        int bA0 = (ooA.x << 4) + kkA.x, bA1 = (ooA.y << 4) + kkA.y;
        int bA2 = (ooA.z << 4) + kkA.z, bA3 = (ooA.w << 4) + kkA.w;
        int bB0 = (ooB.x << 4) + kkB.x, bB1 = (ooB.y << 4) + kkB.y;
        int bB2 = (ooB.z << 4) + kkB.z, bB3 = (ooB.w << 4) + kkB.w;
        int pA0 = atomicAdd(&g_cur[bA0], 1);
        int pA1 = atomicAdd(&g_cur[bA1], 1);
        int pA2 = atomicAdd(&g_cur[bA2], 1);
        int pA3 = atomicAdd(&g_cur[bA3], 1);
        int pB0 = atomicAdd(&g_cur[bB0], 1);
        int pB1 = atomicAdd(&g_cur[bB1], 1);
        int pB2 = atomicAdd(&g_cur[bB2], 1);
        int pB3 = atomicAdd(&g_cur[bB3], 1);
        if (pA0 < CAPK) g_bin[(size_t)bA0 * CAPK + pA0] = make_int2(iiA.x, __float_as_int(ppA.x));
        if (pA1 < CAPK) g_bin[(size_t)bA1 * CAPK + pA1] = make_int2(iiA.y, __float_as_int(ppA.y));
        if (pA2 < CAPK) g_bin[(size_t)bA2 * CAPK + pA2] = make_int2(iiA.z, __float_as_int(ppA.z));
        if (pA3 < CAPK) g_bin[(size_t)bA3 * CAPK + pA3] = make_int2(iiA.w, __float_as_int(ppA.w));
        if (pB0 < CAPK) g_bin[(size_t)bB0 * CAPK + pB0] = make_int2(iiB.x, __float_as_int(ppB.x));
        if (pB1 < CAPK) g_bin[(size_t)bB1 * CAPK + pB1] = make_int2(iiB.y, __float_as_int(ppB.y));
        if (pB2 < CAPK) g_bin[(size_t)bB2 * CAPK + pB2] = make_int2(iiB.z, __float_as_int(ppB.z));
        if (pB3 < CAPK) g_bin[(size_t)bB3 * CAPK + pB3] = make_int2(iiB.w, __float_as_int(ppB.w));
    }
}

__global__ void k_scatter_tail(const int* __restrict__ idx_k,
                               const int* __restrict__ idx_out,
                               const int* __restrict__ idx_in,
                               const float* __restrict__ psi,
                               int start, int nnz) {
    int e = start + blockIdx.x * blockDim.x + threadIdx.x;
    if (e < nnz) {
        int b = (idx_out[e] << 4) + idx_k[e];
        int p = atomicAdd(&g_cur[b], 1);
        if (p < CAPK)
            g_bin[(size_t)b * CAPK + p] = make_int2(idx_in[e], __float_as_int(psi[e]));
    }
}

// ---------------- segment accumulate (fp32 xq: LDG.64 + 2 FFMA per entry) ---
__device__ __forceinline__ void seg_accum(const int4* __restrict__ seg, int cnt,
                                          const float2* __restrict__ xqf,
                                          int lane, float& a0, float& a1) {
    int pairs = cnt >> 1;
    int p = 0;
    for (; p + 2 <= pairs; p += 2) {            // 4 entries, 4 loads in flight
        int4 q0 = seg[p];
        int4 q1 = seg[p + 1];
        float2 f0 = xqf[(q0.x << 5) + lane];
        float2 f1 = xqf[(q0.z << 5) + lane];
        float2 f2 = xqf[(q1.x << 5) + lane];
        float2 f3 = xqf[(q1.z << 5) + lane];
        float p0 = __int_as_float(q0.y), p1 = __int_as_float(q0.w);
        float p2 = __int_as_float(q1.y), p3 = __int_as_float(q1.w);
        a0 = fmaf(p0, f0.x, a0); a1 = fmaf(p0, f0.y, a1);
        a0 = fmaf(p1, f1.x, a0); a1 = fmaf(p1, f1.y, a1);
        a0 = fmaf(p2, f2.x, a0); a1 = fmaf(p2, f2.y, a1);
        a0 = fmaf(p3, f3.x, a0); a1 = fmaf(p3, f3.y, a1);
    }
    for (; p < pairs; p++) {
        int4 q = seg[p];
        float2 f0 = xqf[(q.x << 5) + lane];
        float2 f1 = xqf[(q.z << 5) + lane];
        float p0 = __int_as_float(q.y), p1 = __int_as_float(q.w);
        a0 = fmaf(p0, f0.x, a0); a1 = fmaf(p0, f0.y, a1);
        a0 = fmaf(p1, f1.x, a0); a1 = fmaf(p1, f1.y, a1);
    }
    if (cnt & 1) {
        int2 e = ((const int2*)seg)[cnt - 1];
        float2 f = xqf[(e.x << 5) + lane];
        float ps = __int_as_float(e.y);
        a0 = fmaf(ps, f.x, a0); a1 = fmaf(ps, f.y, a1);
    }
}

// ---------------- K4: fused gather + weight-mix, 2 n per warp ---------------
// 512 thr (16 warps), 4 blocks/SM => 592 resident >= 512 chunks: ONE wave.
// smem: ys 16 warps x 576 half2 (36.9KB); out tile aliased on top.
#define GBLOCKS 592
#define NCHUNK2 (NOUT / 32)      // 512 chunks of 32 n's

__global__ void __launch_bounds__(512, 4) k_gather(const float* __restrict__ bias,
                                                   float* __restrict__ out) {
    extern __shared__ char smem[];
    char*  ysBase = smem;                              // 16 x 2304 B
    float* tile   = (float*)smem;                      // aliased: 64 x 33 floats

    int tid  = threadIdx.x;
    int w    = tid >> 5;
    int lane = tid & 31;

    float bv = bias[lane];
    __half2* ysA = (__half2*)(ysBase + w * 2304);       // [0..287]
    __half2* ysB = ysA + 288;                           // [288..575]
    const float2* __restrict__ xqf = g_xqf;

    for (int chunk = blockIdx.x; chunk < NCHUNK2; chunk += GBLOCKS) {
        int nA = chunk * 32 + w;
        int nB = nA + 16;

        // software-pipelined counts (prefetch k+1 while processing k)
        int cA = g_cur[nA << 4];
        int cB = g_cur[nB << 4];

#pragma unroll
        for (int k = 0; k < KS; k++) {
            int cA_n = 0, cB_n = 0;
            if (k < KS - 1) {
                cA_n = g_cur[(nA << 4) + k + 1];
                cB_n = g_cur[(nB << 4) + k + 1];
            }
            {
                int cnt = cA < CAPK ? cA : CAPK;
                const int4* seg = (const int4*)&g_bin[(size_t)((nA << 4) + k) * CAPK];
                float a0 = 0.f, a1 = 0.f;
                seg_accum(seg, cnt, xqf, lane, a0, a1);
                ysA[k * 32 + lane] = __floats2half2_rn(a0, a1);
            }
            {
                int cnt = cB < CAPK ? cB : CAPK;
                const int4* seg = (const int4*)&g_bin[(size_t)((nB << 4) + k) * CAPK];
                float a0 = 0.f, a1 = 0.f;
                seg_accum(seg, cnt, xqf, lane, a0, a1);
                ysB[k * 32 + lane] = __floats2half2_rn(a0, a1);
            }
            cA = cA_n;
            cB = cB_n;
        }
        __syncwarp();

        // ---- mix: W via L1-resident __ldg; one W read feeds both n's ----
        float accA0 = 0.f, accA1 = 0.f, accB0 = 0.f, accB1 = 0.f;
        const uint2* yA2 = (const uint2*)ysA;
        const uint2* yB2 = (const uint2*)ysB;
        const float2* __restrict__ Wg = (const float2*)g_wT2;
#pragma unroll 2
        for (int jj = 0; jj < 144; jj++) {
            float2 wv = __ldg(&Wg[jj * 32 + lane]);
            uint2 u = yA2[jj];
            float2 y0 = __half22float2(*(__half2*)&u.x);
            float2 y1 = __half22float2(*(__half2*)&u.y);
            accA0 = fmaf(y0.x, wv.x, accA0); accA1 = fmaf(y0.y, wv.x, accA1);
            accA0 = fmaf(y1.x, wv.y, accA0); accA1 = fmaf(y1.y, wv.y, accA1);
            u = yB2[jj];
            y0 = __half22float2(*(__half2*)&u.x);
            y1 = __half22float2(*(__half2*)&u.y);
            accB0 = fmaf(y0.x, wv.x, accB0); accB1 = fmaf(y0.y, wv.x, accB1);
            accB0 = fmaf(y1.x, wv.y, accB0); accB1 = fmaf(y1.y, wv.y, accB1);
        }
        accA0 += bv; accA1 += bv;               // ZSCALE_INV pre-folded into W
        accB0 += bv; accB1 += bv;

        __syncthreads();                        // all warps done reading ys
        tile[lane * 33 + w]             = accA0;   // (b=0, o=lane, col w)
        tile[(32 + lane) * 33 + w]      = accA1;   // (b=1)
        tile[lane * 33 + 16 + w]        = accB0;   // col 16+w
        tile[(32 + lane) * 33 + 16 + w] = accB1;
        __syncthreads();

        int n0 = chunk * 32;
        for (int v = tid; v < 64 * 32; v += 512) {
            int bo = v >> 5;
            int nn = v & 31;
            out[(size_t)bo * NOUT + n0 + nn] = tile[bo * 33 + nn];
        }
        __syncthreads();                        // tile dead before next ys write
    }
}

#define GATHER_SMEM (16 * 2304)

// ---------------- launch: fork scatter chain || prep chain ------------------
extern "C" void kernel_launch(void* const* d_in, const int* in_sizes, int n_in,
                              void* d_out, int out_size) {
    const float* x    = (const float*)d_in[0];
    const float* qw   = (const float*)d_in[1];
    const float* psi  = (const float*)d_in[2];
    const float* wgt  = (const float*)d_in[3];
    const float* bias = (const float*)d_in[4];
    const int* idx_k  = (const int*)d_in[5];
    const int* idx_o  = (const int*)d_in[6];
    const int* idx_i  = (const int*)d_in[7];
    int nnz = in_sizes[2];
    float* out = (float*)d_out;

    cudaFuncSetAttribute(k_gather, cudaFuncAttributeMaxDynamicSharedMemorySize,
                         GATHER_SMEM);

    cudaStream_t s0 = 0;
    cudaStream_t s1;
    cudaStreamCreateWithFlags(&s1, cudaStreamNonBlocking);
    cudaEvent_t evA, evB;
    cudaEventCreateWithFlags(&evA, cudaEventDisableTiming);
    cudaEventCreateWithFlags(&evB, cudaEventDisableTiming);

    int* cur_ptr;
    cudaGetSymbolAddress((void**)&cur_ptr, g_cur);

    // fork: s1 = cursor reset + scatter (depends only on idx arrays)
    cudaEventRecord(evA, s0);
    cudaStreamWaitEvent(s1, evA, 0);
    cudaMemsetAsync(cur_ptr, 0, NOUT * KPAD * sizeof(int), s1);
    int nq8 = nnz >> 3;
    k_scatter8<<<(nq8 + 255) / 256, 256, 0, s1>>>(
        (const int4*)idx_k, (const int4*)idx_o, (const int4*)idx_i,
        (const float4*)psi, nq8);
    int rem = nnz - (nq8 << 3);
    if (rem > 0)
        k_scatter_tail<<<1, 256, 0, s1>>>(idx_k, idx_o, idx_i, psi, nq8 << 3, nnz);
    cudaEventRecord(evB, s1);

    // main stream: xq + wT2 prep
    dim3 tb(32, 32);
    k_xqT<<<dim3(NIN / 32, 64 / 32), tb, 0, s0>>>(x, qw);
    k_wT2<<<(KS * 32 * 32 + 255) / 256, 256, 0, s0>>>(wgt);

    // join, then fused gather+mix (single wave)
    cudaStreamWaitEvent(s0, evB, 0);
    k_gather<<<GBLOCKS, 512, GATHER_SMEM, s0>>>(bias, out);
}